// round 5
// baseline (speedup 1.0000x reference)
#include <cuda_runtime.h>
#include <math_constants.h>

#define NBINS 512
#define KNN   16
#define BATCH 8192
#define NROWS 100000
#define CSB   256         // colsum blocks (32 rows each)
#define RED   16          // reducer blocks folded into main launch

// Scratch (allocation-free rule: __device__ globals). Every element is
// unconditionally written each call -> no zeroing needed.
__device__ float g_part[CSB][NBINS];   // per-block column partial sums
__device__ float g_bcol[NBINS];        // fully reduced column sums
__device__ float g_bsum[BATCH];        // per-batch-row  sum(add)*weight

// Stage 1: column partial sums of outputs[0:BATCH, :]. Runs FIRST so it warms
// L2 with the base-row region main_kernel is about to read. 256 blocks x 32
// rows, thread = column, 4 accumulators for MLP.
__global__ void colsum_kernel(const float* __restrict__ outputs) {
    int col = threadIdx.x;
    int r0  = blockIdx.x * (BATCH / CSB);
    float a0 = 0.0f, a1 = 0.0f, a2 = 0.0f, a3 = 0.0f;
#pragma unroll
    for (int r = 0; r < BATCH / CSB; r += 4) {
        a0 += outputs[(size_t)(r0 + r + 0) * NBINS + col];
        a1 += outputs[(size_t)(r0 + r + 1) * NBINS + col];
        a2 += outputs[(size_t)(r0 + r + 2) * NBINS + col];
        a3 += outputs[(size_t)(r0 + r + 3) * NBINS + col];
    }
    g_part[blockIdx.x][col] = (a0 + a1) + (a2 + a3);
}

// Stage 2 (one launch): blocks [0,RED) reduce g_part -> g_bcol (overlapped
// with the DRAM-bound gather blocks, effectively free); blocks [RED, RED+BATCH)
// do gather+max for one batch row each.
__global__ __launch_bounds__(512, 4)
void main_kernel(const float* __restrict__ outputs,
                 const float* __restrict__ y,
                 const float* __restrict__ weights,
                 float* __restrict__ booster) {
    int tid  = threadIdx.x;
    int warp = tid >> 5;
    int lane = tid & 31;

    if (blockIdx.x < RED) {
        // Reduce 256 partials for 32 columns. Warp w sums 16 rows (coalesced
        // 128B per row across the 32 lanes/columns), then warp 0 combines.
        __shared__ float s_red[RED][32];
        int col = blockIdx.x * 32 + lane;
        float acc = 0.0f;
#pragma unroll
        for (int i = 0; i < CSB / RED; i++)
            acc += g_part[warp * (CSB / RED) + i][col];
        s_red[warp][lane] = acc;
        __syncthreads();
        if (warp == 0) {
            float v = 0.0f;
#pragma unroll
            for (int w = 0; w < RED; w++) v += s_red[w][lane];
            g_bcol[col] = v;
        }
        return;
    }

    // ---- gather + max for batch row b ----
    __shared__ __align__(16) float base[NBINS];
    __shared__ float s_add[KNN];

    int b = blockIdx.x - RED;
    base[tid] = outputs[(size_t)b * NBINS + tid];
    __syncthreads();

    int idx = (int)y[b * KNN + warp];   // trunc; y >= 0
    const float4* g4 = (const float4*)(outputs + (size_t)idx * NBINS);
    const float4* b4 = (const float4*)base;

    float m = -CUDART_INF_F;
#pragma unroll
    for (int t = 0; t < 4; t++) {
        float4 a = g4[t * 32 + lane];
        float4 c = b4[t * 32 + lane];
        m = fmaxf(m, fmaxf(fmaxf(a.x + c.x, a.y + c.y),
                           fmaxf(a.z + c.z, a.w + c.w)));
    }
#pragma unroll
    for (int o = 16; o; o >>= 1)
        m = fmaxf(m, __shfl_xor_sync(0xFFFFFFFFu, m, o));
    if (lane == 0) s_add[warp] = m;
    __syncthreads();

    if (tid == 0) {
        float s = 0.0f;
#pragma unroll
        for (int k = 0; k < KNN; k++) s += s_add[k];
        booster[b] = fmaxf(0.5f, (2.0f - s * (1.0f / KNN)) * 0.5f);
        g_bsum[b]  = s * weights[b];
    }
}

// Stage 3: tiny. Reads g_bcol (2KB) + g_bsum (32KB). 2 barriers.
__global__ void final_kernel(float* __restrict__ out) {
    __shared__ float  smx[16], smn[16];
    __shared__ double ssum[16];
    int t    = threadIdx.x;
    int warp = t >> 5;
    int lane = t & 31;

    float v  = g_bcol[t];
    float mx = v, mn = v;
#pragma unroll
    for (int o = 16; o; o >>= 1) {
        mx = fmaxf(mx, __shfl_xor_sync(0xFFFFFFFFu, mx, o));
        mn = fminf(mn, __shfl_xor_sync(0xFFFFFFFFu, mn, o));
    }

    double ds = 0.0;
#pragma unroll
    for (int i = 0; i < BATCH / 512; i++)
        ds += (double)g_bsum[t + i * 512];
#pragma unroll
    for (int o = 16; o; o >>= 1)
        ds += __shfl_xor_sync(0xFFFFFFFFu, ds, o);

    if (lane == 0) { smx[warp] = mx; smn[warp] = mn; ssum[warp] = ds; }
    __syncthreads();

    if (warp == 0) {
        mx = smx[lane & 15];
        mn = smn[lane & 15];
        ds = ssum[lane & 15];
#pragma unroll
        for (int o = 8; o; o >>= 1) {
            mx = fmaxf(mx, __shfl_xor_sync(0xFFFFFFFFu, mx, o));
            mn = fminf(mn, __shfl_xor_sync(0xFFFFFFFFu, mn, o));
            ds += __shfl_xor_sync(0xFFFFFFFFu, ds, o);
        }
        if (lane == 0) {
            float bb       = mx - mn;
            float target_b = (float)NROWS / (float)NBINS;
            float ratio    = bb / target_b;
            float add_mean = (float)(ds / (double)(BATCH * KNN));
            float d        = 2.0f - add_mean;
            d = d * d;
            out[0] = ratio + d;  // cost
            out[1] = d;          // diff
            out[2] = ratio;      // b / target_b
        }
    }
}

extern "C" void kernel_launch(void* const* d_in, const int* in_sizes, int n_in,
                              void* d_out, int out_size) {
    const float* outputs = (const float*)d_in[0];
    const float* y       = (const float*)d_in[1];
    const float* weights = (const float*)d_in[2];
    float* out = (float*)d_out;

    colsum_kernel<<<CSB, NBINS>>>(outputs);
    main_kernel<<<RED + BATCH, NBINS>>>(outputs, y, weights, out + 3);
    final_kernel<<<1, NBINS>>>(out);
}

// round 7
// speedup vs baseline: 1.6163x; 1.6163x over previous
#include <cuda_runtime.h>
#include <math_constants.h>

#define NBINS 512
#define KNN   16
#define BATCH 8192
#define NROWS 100000
#define CSB   256         // colsum blocks (32 rows each)

// Scratch (__device__ globals: allocation-free rule). Zero-initialized at
// module load; final_kernel re-zeros g_bcol after use, so the "g_bcol == 0 on
// entry" invariant holds for every call (deterministic per-call behavior).
__device__ float g_bcol[NBINS];        // atomic column sums
__device__ float g_bsum[BATCH];        // per-batch-row sum(add)*weight

// One launch: blocks [0, CSB) accumulate column sums of outputs[0:BATCH, :]
// straight into g_bcol via atomics (issued first -> also pre-warms L2 with the
// base-row region the gather blocks read); blocks [CSB, CSB+BATCH) do the
// gather+max for one batch row each.
__global__ __launch_bounds__(512, 4)
void fused_kernel(const float* __restrict__ outputs,
                  const float* __restrict__ y,
                  const float* __restrict__ weights,
                  float* __restrict__ booster) {
    int tid = threadIdx.x;

    if (blockIdx.x < CSB) {
        int r0 = blockIdx.x * (BATCH / CSB);
        float a0 = 0.0f, a1 = 0.0f, a2 = 0.0f, a3 = 0.0f;
#pragma unroll
        for (int r = 0; r < BATCH / CSB; r += 4) {
            a0 += outputs[(size_t)(r0 + r + 0) * NBINS + tid];
            a1 += outputs[(size_t)(r0 + r + 1) * NBINS + tid];
            a2 += outputs[(size_t)(r0 + r + 2) * NBINS + tid];
            a3 += outputs[(size_t)(r0 + r + 3) * NBINS + tid];
        }
        atomicAdd(&g_bcol[tid], (a0 + a1) + (a2 + a3));
        return;
    }

    // ---- gather + max for batch row b ----
    __shared__ __align__(16) float base[NBINS];
    __shared__ float s_add[KNN];

    int b    = blockIdx.x - CSB;
    int warp = tid >> 5;
    int lane = tid & 31;

    base[tid] = outputs[(size_t)b * NBINS + tid];
    __syncthreads();

    int idx = (int)y[b * KNN + warp];   // trunc; y >= 0
    const float4* g4 = (const float4*)(outputs + (size_t)idx * NBINS);
    const float4* b4 = (const float4*)base;

    float m = -CUDART_INF_F;
#pragma unroll
    for (int t = 0; t < 4; t++) {
        float4 a = g4[t * 32 + lane];
        float4 c = b4[t * 32 + lane];
        m = fmaxf(m, fmaxf(fmaxf(a.x + c.x, a.y + c.y),
                           fmaxf(a.z + c.z, a.w + c.w)));
    }
#pragma unroll
    for (int o = 16; o; o >>= 1)
        m = fmaxf(m, __shfl_xor_sync(0xFFFFFFFFu, m, o));
    if (lane == 0) s_add[warp] = m;
    __syncthreads();

    if (tid == 0) {
        float s = 0.0f;
#pragma unroll
        for (int k = 0; k < KNN; k++) s += s_add[k];
        booster[b] = fmaxf(0.5f, (2.0f - s * (1.0f / KNN)) * 0.5f);
        g_bsum[b]  = s * weights[b];
    }
}

// Tiny final: reads g_bcol (2KB) + g_bsum (32KB), 2 barriers, then restores
// the g_bcol == 0 invariant for the next call.
__global__ void final_kernel(float* __restrict__ out) {
    __shared__ float  smx[16], smn[16];
    __shared__ double ssum[16];
    int t    = threadIdx.x;
    int warp = t >> 5;
    int lane = t & 31;

    float v  = g_bcol[t];
    g_bcol[t] = 0.0f;                  // restore invariant
    float mx = v, mn = v;
#pragma unroll
    for (int o = 16; o; o >>= 1) {
        mx = fmaxf(mx, __shfl_xor_sync(0xFFFFFFFFu, mx, o));
        mn = fminf(mn, __shfl_xor_sync(0xFFFFFFFFu, mn, o));
    }

    double ds = 0.0;
#pragma unroll
    for (int i = 0; i < BATCH / 512; i++)
        ds += (double)g_bsum[t + i * 512];
#pragma unroll
    for (int o = 16; o; o >>= 1)
        ds += __shfl_xor_sync(0xFFFFFFFFu, ds, o);

    if (lane == 0) { smx[warp] = mx; smn[warp] = mn; ssum[warp] = ds; }
    __syncthreads();

    if (warp == 0) {
        mx = smx[lane & 15];
        mn = smn[lane & 15];
        ds = ssum[lane & 15];
#pragma unroll
        for (int o = 8; o; o >>= 1) {
            mx = fmaxf(mx, __shfl_xor_sync(0xFFFFFFFFu, mx, o));
            mn = fminf(mn, __shfl_xor_sync(0xFFFFFFFFu, mn, o));
            ds += __shfl_xor_sync(0xFFFFFFFFu, ds, o);
        }
        if (lane == 0) {
            float bb       = mx - mn;
            float target_b = (float)NROWS / (float)NBINS;
            float ratio    = bb / target_b;
            float add_mean = (float)(ds / (double)(BATCH * KNN));
            float d        = 2.0f - add_mean;
            d = d * d;
            out[0] = ratio + d;  // cost
            out[1] = d;          // diff
            out[2] = ratio;      // b / target_b
        }
    }
}

extern "C" void kernel_launch(void* const* d_in, const int* in_sizes, int n_in,
                              void* d_out, int out_size) {
    const float* outputs = (const float*)d_in[0];
    const float* y       = (const float*)d_in[1];
    const float* weights = (const float*)d_in[2];
    float* out = (float*)d_out;

    fused_kernel<<<CSB + BATCH, NBINS>>>(outputs, y, weights, out + 3);
    final_kernel<<<1, NBINS>>>(out);
}

// round 8
// speedup vs baseline: 1.8282x; 1.1311x over previous
#include <cuda_runtime.h>
#include <math_constants.h>

#define NBINS 512
#define KNN   16
#define BATCH 8192
#define NROWS 100000
#define CSB   256         // colsum blocks (32 rows each)

// Scratch (__device__ globals: allocation-free rule). Zero-initialized at
// module load; final_kernel re-zeros both after use, so the "== 0 on entry"
// invariant holds for every call.
__device__ float  g_bcol[NBINS];       // atomic column sums
__device__ double g_sum;               // atomic sum of add*weight

// One launch: blocks [0, CSB) accumulate column sums of outputs[0:BATCH, :]
// straight into g_bcol via atomics (issued first -> pre-warms L2 with the
// base-row region the gather blocks read); blocks [CSB, CSB+BATCH) do the
// gather+max for one batch row each and atomically fold their weighted add
// sum into g_sum (hidden under the DRAM-bound gather stream).
__global__ __launch_bounds__(512, 4)
void fused_kernel(const float* __restrict__ outputs,
                  const float* __restrict__ y,
                  const float* __restrict__ weights,
                  float* __restrict__ booster) {
    int tid = threadIdx.x;

    if (blockIdx.x < CSB) {
        int r0 = blockIdx.x * (BATCH / CSB);
        float a0 = 0.0f, a1 = 0.0f, a2 = 0.0f, a3 = 0.0f;
#pragma unroll
        for (int r = 0; r < BATCH / CSB; r += 4) {
            a0 += outputs[(size_t)(r0 + r + 0) * NBINS + tid];
            a1 += outputs[(size_t)(r0 + r + 1) * NBINS + tid];
            a2 += outputs[(size_t)(r0 + r + 2) * NBINS + tid];
            a3 += outputs[(size_t)(r0 + r + 3) * NBINS + tid];
        }
        atomicAdd(&g_bcol[tid], (a0 + a1) + (a2 + a3));
        return;
    }

    // ---- gather + max for batch row b ----
    __shared__ __align__(16) float base[NBINS];
    __shared__ float s_add[KNN];

    int b    = blockIdx.x - CSB;
    int warp = tid >> 5;
    int lane = tid & 31;

    base[tid] = outputs[(size_t)b * NBINS + tid];
    __syncthreads();

    int idx = (int)y[b * KNN + warp];   // trunc; y >= 0
    const float4* g4 = (const float4*)(outputs + (size_t)idx * NBINS);
    const float4* b4 = (const float4*)base;

    float m = -CUDART_INF_F;
#pragma unroll
    for (int t = 0; t < 4; t++) {
        float4 a = g4[t * 32 + lane];
        float4 c = b4[t * 32 + lane];
        m = fmaxf(m, fmaxf(fmaxf(a.x + c.x, a.y + c.y),
                           fmaxf(a.z + c.z, a.w + c.w)));
    }
#pragma unroll
    for (int o = 16; o; o >>= 1)
        m = fmaxf(m, __shfl_xor_sync(0xFFFFFFFFu, m, o));
    if (lane == 0) s_add[warp] = m;
    __syncthreads();

    if (tid == 0) {
        float s = 0.0f;
#pragma unroll
        for (int k = 0; k < KNN; k++) s += s_add[k];
        booster[b] = fmaxf(0.5f, (2.0f - s * (1.0f / KNN)) * 0.5f);
        atomicAdd(&g_sum, (double)(s * weights[b]));
    }
}

// Tiny final: g_bcol min/max (512 floats) + one scalar read. One barrier.
// Restores the zero-invariants for the next call.
__global__ void final_kernel(float* __restrict__ out) {
    __shared__ float smx[16], smn[16];
    int t    = threadIdx.x;
    int warp = t >> 5;
    int lane = t & 31;

    float v  = g_bcol[t];
    g_bcol[t] = 0.0f;                  // restore invariant
    float mx = v, mn = v;
#pragma unroll
    for (int o = 16; o; o >>= 1) {
        mx = fmaxf(mx, __shfl_xor_sync(0xFFFFFFFFu, mx, o));
        mn = fminf(mn, __shfl_xor_sync(0xFFFFFFFFu, mn, o));
    }
    if (lane == 0) { smx[warp] = mx; smn[warp] = mn; }
    __syncthreads();

    if (t == 0) {
        mx = smx[0]; mn = smn[0];
#pragma unroll
        for (int w = 1; w < 16; w++) {
            mx = fmaxf(mx, smx[w]);
            mn = fminf(mn, smn[w]);
        }
        double ds = g_sum;
        g_sum = 0.0;                   // restore invariant

        float bb       = mx - mn;
        float target_b = (float)NROWS / (float)NBINS;
        float ratio    = bb / target_b;
        float add_mean = (float)(ds / (double)(BATCH * KNN));
        float d        = 2.0f - add_mean;
        d = d * d;
        out[0] = ratio + d;  // cost
        out[1] = d;          // diff
        out[2] = ratio;      // b / target_b
    }
}

extern "C" void kernel_launch(void* const* d_in, const int* in_sizes, int n_in,
                              void* d_out, int out_size) {
    const float* outputs = (const float*)d_in[0];
    const float* y       = (const float*)d_in[1];
    const float* weights = (const float*)d_in[2];
    float* out = (float*)d_out;

    fused_kernel<<<CSB + BATCH, NBINS>>>(outputs, y, weights, out + 3);
    final_kernel<<<1, NBINS>>>(out);
}